// round 7
// baseline (speedup 1.0000x reference)
#include <cuda_runtime.h>
#include <cuda_bf16.h>
#include <mma.h>
#include <math.h>
#include <float.h>

using namespace nvcuda;

// ---------------- problem constants ----------------
#define BB 2048
#define TT 200
#define KK 128
#define UD 128
#define D1 80
#define D2 40
#define DJ 384
#define TPH 208                          // padded t-dim (13 m-tiles of 16)
#define BN_EPS 1e-3f
#define MASKV (-4294967295.0f)
#define RSQRT_K 0.08838834764831843f

// ---- SMEM layout (bytes) for att kernel ----
#define HIST_OFF 0                       // fp32 hist [128][208] = 106496 (wmma A col-major)
#define B1_OFF   106496                  // fp32 WeffT [80][132] = 42240 ; S1 bf16 [208][80]=33280 overlay
#define D1_OFF   148736                  // fp32 D1 [208][80] = 66560 ; D2 [208][52]*4=43264 overlay
#define B2_OFF   215296                  // bf16 W2T [48][80] = 7680
#define MISC_OFF 222976                  // 640 floats = 2560
#define SMEM_ATT_TOTAL 225536

// ---------------- scratch (device globals) ----------
__device__ float g_q[BB * KK];
__device__ float g_cq[BB * D1];
__device__ float g_Wbc[KK * D1];
__device__ float g_Wac[KK * D1];
__device__ float g_obias[BB];
__device__ float g_hist_attn[BB * KK];
__device__ float g_join[BB * DJ];
__device__ float g_y1[BB * D1];
__device__ float g_y2[BB * D2];
__device__ float g_m1[KK],  g_r1[KK];
__device__ float g_m2[DJ],  g_r2[DJ];
__device__ float g_m3[D1],  g_r3[D1];
__device__ float g_m4[D2],  g_r4[D2];

// ---------------- packed fp32x2 helpers ----------------
__device__ __forceinline__ unsigned long long splat2(float x) {
    unsigned long long r;
    asm("mov.b64 %0, {%1, %1};" : "=l"(r) : "f"(x));
    return r;
}
__device__ __forceinline__ unsigned long long pack2(float x, float y) {
    unsigned long long r;
    asm("mov.b64 %0, {%1, %2};" : "=l"(r) : "f"(x), "f"(y));
    return r;
}
__device__ __forceinline__ float2 unpack2(unsigned long long v) {
    float2 r;
    asm("mov.b64 {%0, %1}, %2;" : "=f"(r.x), "=f"(r.y) : "l"(v));
    return r;
}
__device__ __forceinline__ void fma2(unsigned long long& d, unsigned long long a,
                                     unsigned long long b) {
    asm("fma.rn.f32x2 %0, %1, %2, %0;" : "+l"(d) : "l"(a), "l"(b));
}
__device__ __forceinline__ float sigf(float x) {
    float t;
    asm("tanh.approx.f32 %0, %1;" : "=f"(t) : "f"(x * 0.5f));
    return fmaf(0.5f, t, 0.5f);
}
__device__ __forceinline__ float sigf_precise(float x) {
    return __fdividef(1.0f, 1.0f + __expf(-x));
}

// =====================================================================
// prep kernels
// =====================================================================
__global__ void fold_W(const float* __restrict__ W1) {
    int i = blockIdx.x * blockDim.x + threadIdx.x;
    if (i < KK * D1) {
        int k = i / D1, j = i - k * D1;
        float a = W1[(size_t)k * D1 + j];
        float b = W1[(size_t)(KK + k) * D1 + j];
        float c = W1[(size_t)(2 * KK + k) * D1 + j];
        g_Wbc[i] = b - c;
        g_Wac[i] = a + c;
    }
}

__global__ void prep_batch(const int* __restrict__ user, const int* __restrict__ item,
                           const int* __restrict__ cate_list,
                           const float* __restrict__ user_table,
                           const float* __restrict__ item_table,
                           const float* __restrict__ cate_table,
                           const float* __restrict__ item_bias) {
    int b = blockIdx.x, tid = threadIdx.x;
    int it = item[b];
    float qv = (tid < 64) ? item_table[(size_t)it * 64 + tid]
                          : cate_table[(size_t)cate_list[it] * 64 + (tid - 64)];
    g_q[b * KK + tid] = qv;
    g_join[b * DJ + UD + tid] = qv;
    g_join[b * DJ + tid] = user_table[(size_t)user[b] * UD + tid];
    if (tid == 0) g_obias[b] = item_bias[it];
}

// =====================================================================
// SMEM-staged tail GEMM (proven in R4)
// =====================================================================
template<int KIN, int JOUT, int MODE>
__global__ __launch_bounds__(256) void gemm_smemW(
    const float* __restrict__ in, int in_stride,
    const float* __restrict__ W, const float* __restrict__ bias,
    float* __restrict__ out, int out_stride, int out_off,
    const float* __restrict__ mean, const float* __restrict__ rstd,
    const float* __restrict__ p1, const float* __restrict__ p2)
{
    constexpr int KP  = KIN + 2;
    constexpr int NR  = 256 / JOUT;
    constexpr int ACT = NR * JOUT;
    constexpr int M   = (16 + NR - 1) / NR;
    extern __shared__ float smg[];
    float* ws = smg;
    float* xs = ws + JOUT * KP;
    const int b0 = blockIdx.x * 16;

    for (int i = threadIdx.x; i < KIN * JOUT; i += 256) {
        int k = i / JOUT, j = i - k * JOUT;
        ws[j * KP + k] = W[i];
    }
    for (int i = threadIdx.x; i < 16 * KIN; i += 256) {
        int r = i / KIN, k = i - r * KIN;
        float v = in[(size_t)(b0 + r) * in_stride + k];
        if constexpr (MODE == 1) {
            v = (v - mean[k]) * rstd[k] * p1[k] + p2[k];
        } else if constexpr (MODE == 2) {
            float xn = (v - mean[k]) * rstd[k];
            float pp = sigf(p2[k] * xn);
            v = v * (pp + p1[k] * (1.0f - pp));
        }
        xs[r * KP + k] = v;
    }
    __syncthreads();

    if (threadIdx.x < ACT) {
        const int j  = threadIdx.x % JOUT;
        const int rg = threadIdx.x / JOUT;
        const float bj = bias[j];
        unsigned long long acc[M];
        const unsigned long long* xpr[M];
#pragma unroll
        for (int m = 0; m < M; m++) {
            acc[m] = 0ULL;
            xpr[m] = (const unsigned long long*)(xs + (rg + NR * m) * KP);
        }
        const unsigned long long* wp = (const unsigned long long*)(ws + j * KP);
#pragma unroll 4
        for (int kp = 0; kp < KIN / 2; kp++) {
            unsigned long long w2 = wp[kp];
#pragma unroll
            for (int m = 0; m < M; m++)
                fma2(acc[m], xpr[m][kp], w2);
        }
#pragma unroll
        for (int m = 0; m < M; m++) {
            int r = rg + NR * m;
            if (r < 16) {
                float2 v = unpack2(acc[m]);
                out[(size_t)(b0 + r) * out_stride + out_off + j] = v.x + v.y + bj;
            }
        }
    }
}

__global__ void colstats2(const float* __restrict__ x, int rows, int cols,
                          float* __restrict__ mean, float* __restrict__ rstd)
{
    __shared__ float ss[16][33], sq[16][33];
    int tx = threadIdx.x & 31, ty = threadIdx.x >> 5;
    int col = blockIdx.x * 32 + tx;
    float s = 0.f, q = 0.f;
    if (col < cols) {
#pragma unroll 8
        for (int r = ty; r < rows; r += 16) {
            float v = x[(size_t)r * cols + col];
            s += v; q = fmaf(v, v, q);
        }
    }
    ss[ty][tx] = s; sq[ty][tx] = q;
    __syncthreads();
    if (ty == 0 && col < cols) {
        float S = 0.f, Q = 0.f;
#pragma unroll
        for (int i = 0; i < 16; i++) { S += ss[i][tx]; Q += sq[i][tx]; }
        float m = S / (float)rows;
        float v = Q / (float)rows - m * m;
        mean[col] = m;
        rstd[col] = rsqrtf(v + BN_EPS);
    }
}

// =====================================================================
// fused DIN attention: one CTA per batch row, WMMA (tf32 L1, bf16 L2)
// =====================================================================
__global__ __launch_bounds__(256, 1) void att_kernel(
    const int* __restrict__ history, const int* __restrict__ length,
    const int* __restrict__ cate_list,
    const float* __restrict__ item_table, const float* __restrict__ cate_table,
    const float* __restrict__ W1,
    const float* __restrict__ W2, const float* __restrict__ b2,
    const float* __restrict__ W3, const float* __restrict__ b3)
{
    extern __shared__ __align__(16) char smc[];
    float* hist_s = (float*)(smc + HIST_OFF);            // [128][208] k-major (wmma A col-major)
    float* b1f    = (float*)(smc + B1_OFF);              // [80][132] WeffT fp32
    __nv_bfloat16* s1p = (__nv_bfloat16*)(smc + B1_OFF); // S1 overlay [208][80] bf16
    float* d1f    = (float*)(smc + D1_OFF);              // [208][80] fp32
    float* d2f    = (float*)(smc + D1_OFF);              // D2 overlay [208][52] fp32
    __nv_bfloat16* b2f = (__nv_bfloat16*)(smc + B2_OFF); // [48][80] bf16
    float* cqs  = (float*)(smc + MISC_OFF);              // 80
    float* w3s  = cqs + 80;                              // 40
    float* b2s  = w3s + 40;                              // 40
    float* red  = b2s + 40;                              // 256
    float* attn = red + 256;                             // 224

    const int b   = blockIdx.x;
    const int tid = threadIdx.x;
    const int wid = tid >> 5;
    const int len = length[b];

    if (tid < D1) cqs[tid] = g_cq[b * D1 + tid];
    if (tid < D2) { w3s[tid] = W3[tid]; b2s[tid] = b2[tid]; }

    // zero hist cols [len, 208)
    {
        int k = tid & 127;
        for (int t = len + (tid >> 7); t < TPH; t += 2)
            hist_s[k * TPH + t] = 0.0f;
    }

    // B1 = WeffT fp32: b1f[n*132+k] = Wbc[k][n] + q_k * W1d[k][n]
    for (int i = tid; i < KK * D1; i += 256) {
        int k = i / D1, n = i - k * D1;
        float qk = g_q[b * KK + k];
        b1f[n * 132 + k] = fmaf(qk, W1[(size_t)(3 * KK + k) * D1 + n], g_Wbc[i]);
    }
    // B2 = W2T bf16: b2f[n*80+k] = W2[k][n]; rows n in [40,48) zero
    for (int i = tid; i < D1 * D2; i += 256) {
        int k = i / D2, n = i - k * D2;
        b2f[n * 80 + k] = __float2bfloat16(W2[i]);
    }
    for (int i = tid; i < 8 * 80; i += 256)
        b2f[40 * 80 + i] = __float2bfloat16(0.0f);

    // gather hist (only t < len), k-major
    if (tid < len) {
        const int t    = tid;
        const int hidx = history[b * TT + t];
        const int hc   = cate_list[hidx];
        const float4* irow = (const float4*)(item_table + (size_t)hidx * 64);
        const float4* crow = (const float4*)(cate_table + (size_t)hc * 64);
#pragma unroll
        for (int c = 0; c < 16; c++) {
            float4 v = irow[c];
            int kb = 4 * c;
            hist_s[(kb + 0) * TPH + t] = v.x;
            hist_s[(kb + 1) * TPH + t] = v.y;
            hist_s[(kb + 2) * TPH + t] = v.z;
            hist_s[(kb + 3) * TPH + t] = v.w;
        }
#pragma unroll
        for (int c = 0; c < 16; c++) {
            float4 v = crow[c];
            int kb = 64 + 4 * c;
            hist_s[(kb + 0) * TPH + t] = v.x;
            hist_s[(kb + 1) * TPH + t] = v.y;
            hist_s[(kb + 2) * TPH + t] = v.z;
            hist_s[(kb + 3) * TPH + t] = v.w;
        }
    }
    __syncthreads();

    // ---- layer 1: D1[208x80] = hist[208x128] @ Weff[128x80]  (tf32 wmma) ----
    for (int idx = wid; idx < 13 * 5; idx += 8) {
        int mt = idx / 5, nt = idx - 5 * mt;
        wmma::fragment<wmma::accumulator, 16, 16, 8, float> c;
        wmma::fill_fragment(c, 0.0f);
#pragma unroll 4
        for (int ks = 0; ks < 16; ks++) {
            wmma::fragment<wmma::matrix_a, 16, 16, 8, wmma::precision::tf32,
                           wmma::col_major> af;
            wmma::fragment<wmma::matrix_b, 16, 16, 8, wmma::precision::tf32,
                           wmma::col_major> bf;
            wmma::load_matrix_sync(af, hist_s + ks * 8 * TPH + mt * 16, TPH);
            wmma::load_matrix_sync(bf, b1f + nt * 16 * 132 + ks * 8, 132);
#pragma unroll
            for (int e = 0; e < af.num_elements; e++)
                af.x[e] = wmma::__float_to_tf32(af.x[e]);
#pragma unroll
            for (int e = 0; e < bf.num_elements; e++)
                bf.x[e] = wmma::__float_to_tf32(bf.x[e]);
            wmma::mma_sync(c, af, bf, c);
        }
        wmma::store_matrix_sync(d1f + mt * 16 * D1 + nt * 16, c, D1,
                                wmma::mem_row_major);
    }
    __syncthreads();

    // ---- epilogue 1: S1 = sigf(D1 + cq) -> bf16 (overlays B1) ----
    for (int i = tid; i < TPH * D1; i += 256) {
        int j = i % D1;
        s1p[i] = __float2bfloat16(sigf(d1f[i] + cqs[j]));
    }
    __syncthreads();

    // ---- layer 2: D2[208x48] = S1[208x80] @ W2[80x40pad48]  (bf16 wmma) ----
    for (int idx = wid; idx < 13 * 3; idx += 8) {
        int mt = idx / 3, nt = idx - 3 * mt;
        wmma::fragment<wmma::accumulator, 16, 16, 16, float> c;
        wmma::fill_fragment(c, 0.0f);
#pragma unroll
        for (int ks = 0; ks < 5; ks++) {
            wmma::fragment<wmma::matrix_a, 16, 16, 16, __nv_bfloat16,
                           wmma::row_major> af;
            wmma::fragment<wmma::matrix_b, 16, 16, 16, __nv_bfloat16,
                           wmma::col_major> bf;
            wmma::load_matrix_sync(af, s1p + mt * 16 * 80 + ks * 16, 80);
            wmma::load_matrix_sync(bf, b2f + nt * 16 * 80 + ks * 16, 80);
            wmma::mma_sync(c, af, bf, c);
        }
        wmma::store_matrix_sync(d2f + mt * 16 * 52 + nt * 16, c, 52,
                                wmma::mem_row_major);
    }
    __syncthreads();

    // ---- layer 3 + score ----
    float sc = -FLT_MAX;
    if (tid < TT) {
        if (tid < len) {
            float score = b3[0];
            const float* dr = d2f + tid * 52;
#pragma unroll
            for (int n = 0; n < D2; n++)
                score = fmaf(sigf(dr[n] + b2s[n]), w3s[n], score);
            sc = score * RSQRT_K;
        } else {
            sc = MASKV * RSQRT_K;
        }
    }

    // ---- softmax over t ----
    red[tid] = sc;
    __syncthreads();
#pragma unroll
    for (int s = 128; s > 0; s >>= 1) {
        if (tid < s) red[tid] = fmaxf(red[tid], red[tid + s]);
        __syncthreads();
    }
    const float mx = red[0];
    __syncthreads();
    float p = 0.0f;
    if (tid < TT) p = __expf(sc - mx);
    red[tid] = p;
    __syncthreads();
#pragma unroll
    for (int s = 128; s > 0; s >>= 1) {
        if (tid < s) red[tid] += red[tid + s];
        __syncthreads();
    }
    const float inv = 1.0f / red[0];
    if (tid < 224) attn[tid] = (tid < TT) ? p * inv : 0.0f;
    __syncthreads();

    // ---- hist_attn[k] = sum_t attn[t] * hist[k][t] (fp32 exact) ----
    if (tid < KK) {
        const float2* hp = (const float2*)(hist_s + tid * TPH);
        const float2* ap = (const float2*)attn;
        unsigned long long acc = 0ULL;
#pragma unroll 4
        for (int t2 = 0; t2 < TPH / 2; t2++) {
            float2 av = ap[t2];
            float2 hv = hp[t2];
            fma2(acc, pack2(av.x, av.y), pack2(hv.x, hv.y));
        }
        float2 r = unpack2(acc);
        g_hist_attn[b * KK + tid] = r.x + r.y;
    }
}

// =====================================================================
// final: dice + fc3 + item bias + sigmoid
// =====================================================================
__global__ void final_k(const float* __restrict__ W3, const float* __restrict__ b3,
                        const float* __restrict__ alpha, const float* __restrict__ beta,
                        float* __restrict__ out, int out_size)
{
    int b = blockIdx.x * blockDim.x + threadIdx.x;
    if (b >= BB) return;
    float acc = b3[0];
#pragma unroll
    for (int k = 0; k < D2; k++) {
        float v  = g_y2[b * D2 + k];
        float xn = (v - g_m4[k]) * g_r4[k];
        float pp = sigf(beta[k] * xn);
        v = v * (pp + alpha[k] * (1.0f - pp));
        acc = fmaf(v, W3[k], acc);
    }
    acc += g_obias[b];
    if (b < out_size) out[b] = acc;
    if (BB + b < out_size) out[BB + b] = sigf_precise(acc);
}

// =====================================================================
// launch
// =====================================================================
extern "C" void kernel_launch(void* const* d_in, const int* in_sizes, int n_in,
                              void* d_out, int out_size)
{
    const int*   user       = (const int*)  d_in[0];
    const int*   item       = (const int*)  d_in[1];
    const int*   history    = (const int*)  d_in[2];
    const int*   length     = (const int*)  d_in[3];
    const int*   cate_list  = (const int*)  d_in[4];
    const float* user_table = (const float*)d_in[5];
    const float* item_table = (const float*)d_in[6];
    const float* cate_table = (const float*)d_in[7];
    const float* item_bias  = (const float*)d_in[8];
    const float* att_W1     = (const float*)d_in[9];
    const float* att_b1     = (const float*)d_in[10];
    const float* att_W2     = (const float*)d_in[11];
    const float* att_b2     = (const float*)d_in[12];
    const float* att_W3     = (const float*)d_in[13];
    const float* att_b3     = (const float*)d_in[14];
    const float* hbn_gamma  = (const float*)d_in[15];
    const float* hbn_beta   = (const float*)d_in[16];
    const float* hist_W     = (const float*)d_in[17];
    const float* hist_b     = (const float*)d_in[18];
    const float* fbn_gamma  = (const float*)d_in[19];
    const float* fbn_beta   = (const float*)d_in[20];
    const float* fc1_W      = (const float*)d_in[21];
    const float* fc1_b      = (const float*)d_in[22];
    const float* d1_alpha   = (const float*)d_in[23];
    const float* d1_beta    = (const float*)d_in[24];
    const float* fc2_W      = (const float*)d_in[25];
    const float* fc2_b      = (const float*)d_in[26];
    const float* d2_alpha   = (const float*)d_in[27];
    const float* d2_beta    = (const float*)d_in[28];
    const float* fc3_W      = (const float*)d_in[29];
    const float* fc3_b      = (const float*)d_in[30];
    float* out = (float*)d_out;

    float *p_q, *p_cq, *p_wac, *p_ha, *p_join, *p_y1, *p_y2;
    float *p_m1, *p_r1, *p_m2, *p_r2, *p_m3, *p_r3, *p_m4, *p_r4;
    cudaGetSymbolAddress((void**)&p_q,    g_q);
    cudaGetSymbolAddress((void**)&p_cq,   g_cq);
    cudaGetSymbolAddress((void**)&p_wac,  g_Wac);
    cudaGetSymbolAddress((void**)&p_ha,   g_hist_attn);
    cudaGetSymbolAddress((void**)&p_join, g_join);
    cudaGetSymbolAddress((void**)&p_y1,   g_y1);
    cudaGetSymbolAddress((void**)&p_y2,   g_y2);
    cudaGetSymbolAddress((void**)&p_m1,   g_m1);
    cudaGetSymbolAddress((void**)&p_r1,   g_r1);
    cudaGetSymbolAddress((void**)&p_m2,   g_m2);
    cudaGetSymbolAddress((void**)&p_r2,   g_r2);
    cudaGetSymbolAddress((void**)&p_m3,   g_m3);
    cudaGetSymbolAddress((void**)&p_r3,   g_r3);
    cudaGetSymbolAddress((void**)&p_m4,   g_m4);
    cudaGetSymbolAddress((void**)&p_r4,   g_r4);

    cudaFuncSetAttribute(att_kernel, cudaFuncAttributeMaxDynamicSharedMemorySize,
                         SMEM_ATT_TOTAL);

    auto smemG = [](int KIN, int JOUT) { return (JOUT + 18) * (KIN + 2) * 4; };
    cudaFuncSetAttribute((const void*)gemm_smemW<128, 80, 0>,
        cudaFuncAttributeMaxDynamicSharedMemorySize, smemG(128, 80));
    cudaFuncSetAttribute((const void*)gemm_smemW<128, 128, 1>,
        cudaFuncAttributeMaxDynamicSharedMemorySize, smemG(128, 128));
    cudaFuncSetAttribute((const void*)gemm_smemW<384, 80, 1>,
        cudaFuncAttributeMaxDynamicSharedMemorySize, smemG(384, 80));
    cudaFuncSetAttribute((const void*)gemm_smemW<80, 40, 2>,
        cudaFuncAttributeMaxDynamicSharedMemorySize, smemG(80, 40));

    // 1-3: prep (att lands in profile slot 4)
    fold_W<<<(KK * D1 + 255) / 256, 256>>>(att_W1);
    prep_batch<<<BB, 128>>>(user, item, cate_list, user_table, item_table,
                            cate_table, item_bias);
    gemm_smemW<128, 80, 0><<<BB / 16, 256, smemG(128, 80)>>>(
        p_q, KK, p_wac, att_b1, p_cq, D1, 0, nullptr, nullptr, nullptr, nullptr);

    // 4: fused DIN attention (wmma)
    att_kernel<<<BB, 256, SMEM_ATT_TOTAL>>>(history, length, cate_list,
                                            item_table, cate_table,
                                            att_W1, att_W2, att_b2, att_W3, att_b3);

    // tail
    colstats2<<<(KK + 31) / 32, 512>>>(p_ha, BB, KK, p_m1, p_r1);
    gemm_smemW<128, 128, 1><<<BB / 16, 256, smemG(128, 128)>>>(
        p_ha, KK, hist_W, hist_b, p_join, DJ, 256, p_m1, p_r1, hbn_gamma, hbn_beta);
    colstats2<<<(DJ + 31) / 32, 512>>>(p_join, BB, DJ, p_m2, p_r2);
    gemm_smemW<384, 80, 1><<<BB / 16, 256, smemG(384, 80)>>>(
        p_join, DJ, fc1_W, fc1_b, p_y1, D1, 0, p_m2, p_r2, fbn_gamma, fbn_beta);
    colstats2<<<(D1 + 31) / 32, 512>>>(p_y1, BB, D1, p_m3, p_r3);
    gemm_smemW<80, 40, 2><<<BB / 16, 256, smemG(80, 40)>>>(
        p_y1, D1, fc2_W, fc2_b, p_y2, D2, 0, p_m3, p_r3, d1_alpha, d1_beta);
    colstats2<<<(D2 + 31) / 32, 512>>>(p_y2, BB, D2, p_m4, p_r4);
    final_k<<<(BB + 255) / 256, 256>>>(fc3_W, fc3_b, d2_alpha, d2_beta, out, out_size);
}

// round 8
// speedup vs baseline: 1.0768x; 1.0768x over previous
#include <cuda_runtime.h>
#include <cuda_bf16.h>
#include <mma.h>
#include <math.h>
#include <float.h>

using namespace nvcuda;

// ---------------- problem constants ----------------
#define BB 2048
#define TT 200
#define KK 128
#define UD 128
#define D1 80
#define D2 40
#define DJ 384
#define TPH 208                          // padded t (13 m-tiles)
#define ALD 264                          // A ldm (bf16 elems): 528B rows, bank-staggered
#define BN_EPS 1e-3f
#define MASKV (-4294967295.0f)
#define RSQRT_K 0.08838834764831843f

// ---- ATT-A SMEM layout (bytes) ----
#define A_OFF    0                       // bf16 A [208][264] = 109824 ; D1/D2 fp32 overlay
#define B1S_OFF  109824                  // bf16 B1 [80][256] = 40960
#define S1_OFF   150784                  // bf16 S1 [208][80] = 33280
#define B2S_OFF  184064                  // bf16 B2 [48][80]  = 7680
#define MISC_OFF 191744                  // fp32: qs128 cqs80 w3s40 b2s40 red512
#define SMEM_ATT_TOTAL 194944

// ---------------- scratch (device globals) ----------
__device__ float g_q[BB * KK];
__device__ float g_cq[BB * D1];
__device__ float g_Wac[KK * D1];
__device__ __nv_bfloat16 g_B1bf[D1 * 256];   // [n][k] k-contig: k<128 Wbc, k>=128 W1d
__device__ __nv_bfloat16 g_B2bf[48 * D1];    // [n][k] W2^T padded to 48 n
__device__ float g_attn[BB * 224];
__device__ float g_obias[BB];
__device__ float g_hist_attn[BB * KK];
__device__ float g_join[BB * DJ];
__device__ float g_y1[BB * D1];
__device__ float g_y2[BB * D2];
__device__ float g_m1[KK],  g_r1[KK];
__device__ float g_m2[DJ],  g_r2[DJ];
__device__ float g_m3[D1],  g_r3[D1];
__device__ float g_m4[D2],  g_r4[D2];

// ---------------- helpers ----------------
__device__ __forceinline__ unsigned long long pack2(float x, float y) {
    unsigned long long r;
    asm("mov.b64 %0, {%1, %2};" : "=l"(r) : "f"(x), "f"(y));
    return r;
}
__device__ __forceinline__ float2 unpack2(unsigned long long v) {
    float2 r;
    asm("mov.b64 {%0, %1}, %2;" : "=f"(r.x), "=f"(r.y) : "l"(v));
    return r;
}
__device__ __forceinline__ unsigned long long splat2(float x) {
    unsigned long long r;
    asm("mov.b64 %0, {%1, %1};" : "=l"(r) : "f"(x));
    return r;
}
__device__ __forceinline__ void fma2(unsigned long long& d, unsigned long long a,
                                     unsigned long long b) {
    asm("fma.rn.f32x2 %0, %1, %2, %0;" : "+l"(d) : "l"(a), "l"(b));
}
__device__ __forceinline__ float sigf(float x) {
    float t;
    asm("tanh.approx.f32 %0, %1;" : "=f"(t) : "f"(x * 0.5f));
    return fmaf(0.5f, t, 0.5f);
}
__device__ __forceinline__ float sigf_precise(float x) {
    return __fdividef(1.0f, 1.0f + __expf(-x));
}
// pack 2 fp32 -> bf16x2, x in low half
__device__ __forceinline__ unsigned int bf16x2_of(float x, float y) {
    unsigned int r;
    asm("cvt.rn.bf16x2.f32 %0, %2, %1;" : "=r"(r) : "f"(x), "f"(y));
    return r;
}

// =====================================================================
// fold: build g_Wac (fp32) + fixed bf16 B1 [80][256] + B2 [48][80]
// grid 95 x 256 = 24320 threads
// =====================================================================
__global__ void fold_W(const float* __restrict__ W1, const float* __restrict__ W2) {
    int i = blockIdx.x * blockDim.x + threadIdx.x;
    if (i < KK * D1) {   // g_Wac[k*80+n]
        int k = i / D1, n = i - k * D1;
        g_Wac[i] = W1[(size_t)k * D1 + n] + W1[(size_t)(2 * KK + k) * D1 + n];
    }
    if (i < D1 * 256) {  // g_B1bf[n*256+k]
        int n = i >> 8, k = i & 255;
        float w;
        if (k < 128)
            w = W1[(size_t)(KK + k) * D1 + n] - W1[(size_t)(2 * KK + k) * D1 + n];
        else
            w = W1[(size_t)(3 * KK + (k - 128)) * D1 + n];
        g_B1bf[i] = __float2bfloat16(w);
    }
    int j = i - D1 * 256;
    if (j >= 0 && j < 48 * D1) {  // g_B2bf[n*80+k]
        int n = j / D1, k = j - n * D1;
        g_B2bf[j] = (n < D2) ? __float2bfloat16(W2[(size_t)k * D2 + n])
                             : __float2bfloat16(0.0f);
    }
}

__global__ void prep_batch(const int* __restrict__ user, const int* __restrict__ item,
                           const int* __restrict__ cate_list,
                           const float* __restrict__ user_table,
                           const float* __restrict__ item_table,
                           const float* __restrict__ cate_table,
                           const float* __restrict__ item_bias) {
    int b = blockIdx.x, tid = threadIdx.x;
    int it = item[b];
    float qv = (tid < 64) ? item_table[(size_t)it * 64 + tid]
                          : cate_table[(size_t)cate_list[it] * 64 + (tid - 64)];
    g_q[b * KK + tid] = qv;
    g_join[b * DJ + UD + tid] = qv;
    g_join[b * DJ + tid] = user_table[(size_t)user[b] * UD + tid];
    if (tid == 0) g_obias[b] = item_bias[it];
}

// =====================================================================
// SMEM-staged tail GEMM (proven R4)
// =====================================================================
template<int KIN, int JOUT, int MODE>
__global__ __launch_bounds__(256) void gemm_smemW(
    const float* __restrict__ in, int in_stride,
    const float* __restrict__ W, const float* __restrict__ bias,
    float* __restrict__ out, int out_stride, int out_off,
    const float* __restrict__ mean, const float* __restrict__ rstd,
    const float* __restrict__ p1, const float* __restrict__ p2)
{
    constexpr int KP  = KIN + 2;
    constexpr int NR  = 256 / JOUT;
    constexpr int ACT = NR * JOUT;
    constexpr int M   = (16 + NR - 1) / NR;
    extern __shared__ float smg[];
    float* ws = smg;
    float* xs = ws + JOUT * KP;
    const int b0 = blockIdx.x * 16;

    for (int i = threadIdx.x; i < KIN * JOUT; i += 256) {
        int k = i / JOUT, j = i - k * JOUT;
        ws[j * KP + k] = W[i];
    }
    for (int i = threadIdx.x; i < 16 * KIN; i += 256) {
        int r = i / KIN, k = i - r * KIN;
        float v = in[(size_t)(b0 + r) * in_stride + k];
        if constexpr (MODE == 1) {
            v = (v - mean[k]) * rstd[k] * p1[k] + p2[k];
        } else if constexpr (MODE == 2) {
            float xn = (v - mean[k]) * rstd[k];
            float pp = sigf(p2[k] * xn);
            v = v * (pp + p1[k] * (1.0f - pp));
        }
        xs[r * KP + k] = v;
    }
    __syncthreads();

    if (threadIdx.x < ACT) {
        const int j  = threadIdx.x % JOUT;
        const int rg = threadIdx.x / JOUT;
        const float bj = bias[j];
        unsigned long long acc[M];
        const unsigned long long* xpr[M];
#pragma unroll
        for (int m = 0; m < M; m++) {
            acc[m] = 0ULL;
            xpr[m] = (const unsigned long long*)(xs + (rg + NR * m) * KP);
        }
        const unsigned long long* wp = (const unsigned long long*)(ws + j * KP);
#pragma unroll 4
        for (int kp = 0; kp < KIN / 2; kp++) {
            unsigned long long w2 = wp[kp];
#pragma unroll
            for (int m = 0; m < M; m++)
                fma2(acc[m], xpr[m][kp], w2);
        }
#pragma unroll
        for (int m = 0; m < M; m++) {
            int r = rg + NR * m;
            if (r < 16) {
                float2 v = unpack2(acc[m]);
                out[(size_t)(b0 + r) * out_stride + out_off + j] = v.x + v.y + bj;
            }
        }
    }
}

__global__ void colstats2(const float* __restrict__ x, int rows, int cols,
                          float* __restrict__ mean, float* __restrict__ rstd)
{
    __shared__ float ss[16][33], sq[16][33];
    int tx = threadIdx.x & 31, ty = threadIdx.x >> 5;
    int col = blockIdx.x * 32 + tx;
    float s = 0.f, q = 0.f;
    if (col < cols) {
#pragma unroll 8
        for (int r = ty; r < rows; r += 16) {
            float v = x[(size_t)r * cols + col];
            s += v; q = fmaf(v, v, q);
        }
    }
    ss[ty][tx] = s; sq[ty][tx] = q;
    __syncthreads();
    if (ty == 0 && col < cols) {
        float S = 0.f, Q = 0.f;
#pragma unroll
        for (int i = 0; i < 16; i++) { S += ss[i][tx]; Q += sq[i][tx]; }
        float m = S / (float)rows;
        float v = Q / (float)rows - m * m;
        mean[col] = m;
        rstd[col] = rsqrtf(v + BN_EPS);
    }
}

// =====================================================================
// ATT-A: per-batch scores + softmax. bf16 wmma, fixed weights, 512 thr.
// =====================================================================
__global__ __launch_bounds__(512, 1) void att_kernel(
    const int* __restrict__ history, const int* __restrict__ length,
    const int* __restrict__ cate_list,
    const float* __restrict__ item_table, const float* __restrict__ cate_table,
    const float* __restrict__ b2, const float* __restrict__ W3,
    const float* __restrict__ b3)
{
    extern __shared__ __align__(16) char smc[];
    __nv_bfloat16* a_bf = (__nv_bfloat16*)(smc + A_OFF);    // [208][264]
    float*         d1f  = (float*)(smc + A_OFF);            // overlay [208][80]
    float*         d2f  = (float*)(smc + A_OFF);            // overlay [208][52]
    __nv_bfloat16* b1s  = (__nv_bfloat16*)(smc + B1S_OFF);  // [80][256]
    __nv_bfloat16* s1p  = (__nv_bfloat16*)(smc + S1_OFF);   // [208][80]
    __nv_bfloat16* b2s  = (__nv_bfloat16*)(smc + B2S_OFF);  // [48][80]
    float* qs  = (float*)(smc + MISC_OFF);                  // 128
    float* cqs = qs + 128;                                  // 80
    float* w3s = cqs + 80;                                  // 40
    float* b2v = w3s + 40;                                  // 40
    float* red = b2v + 40;                                  // 512

    const int b   = blockIdx.x;
    const int tid = threadIdx.x;
    const int wid = tid >> 5;
    const int len = length[b];

    // ---- phase 0: stage small params, zero A ----
    if (tid < KK) qs[tid] = g_q[b * KK + tid];
    else if (tid < KK + D1) cqs[tid - KK] = g_cq[b * D1 + (tid - KK)];
    else if (tid < KK + D1 + D2) w3s[tid - KK - D1] = W3[tid - KK - D1];
    else if (tid < KK + D1 + 2 * D2) b2v[tid - KK - D1 - D2] = b2[tid - KK - D1 - D2];
    {
        uint4 z = make_uint4(0, 0, 0, 0);
        uint4* ap = (uint4*)a_bf;
        for (int i = tid; i < (TPH * ALD * 2) / 16; i += 512) ap[i] = z;
    }
    // stage B1, B2 (coalesced copies of prefolded bf16)
    {
        const uint4* src = (const uint4*)g_B1bf;
        uint4* dst = (uint4*)b1s;
        for (int i = tid; i < (D1 * 256 * 2) / 16; i += 512) dst[i] = src[i];
        const uint4* s2 = (const uint4*)g_B2bf;
        uint4* dd = (uint4*)b2s;
        if (tid < (48 * D1 * 2) / 16) dd[tid] = s2[tid];
    }
    __syncthreads();

    // ---- gather + A build: thread (t, half) ----
    {
        int t = tid >> 1, half = tid & 1;
        if (t < len) {
            int hidx = history[b * TT + t];
            const float4* row = half
                ? (const float4*)(cate_table + (size_t)cate_list[hidx] * 64)
                : (const float4*)(item_table + (size_t)hidx * 64);
            int kb0 = half * 64;
            __nv_bfloat16* arow = a_bf + t * ALD;
#pragma unroll
            for (int c = 0; c < 16; c++) {
                float4 v = row[c];
                int k = kb0 + 4 * c;
                *(unsigned int*)(arow + k)     = bf16x2_of(v.x, v.y);
                *(unsigned int*)(arow + k + 2) = bf16x2_of(v.z, v.w);
                *(unsigned int*)(arow + 128 + k)     = bf16x2_of(qs[k] * v.x, qs[k + 1] * v.y);
                *(unsigned int*)(arow + 128 + k + 2) = bf16x2_of(qs[k + 2] * v.z, qs[k + 3] * v.w);
            }
        }
    }
    __syncthreads();

    // ---- layer 1: D1[208x80] = A[208x256] @ B1^T  (bf16 wmma) ----
    wmma::fragment<wmma::accumulator, 16, 16, 16, float> acc1[5];
    if (wid < 13) {
#pragma unroll
        for (int nt = 0; nt < 5; nt++) wmma::fill_fragment(acc1[nt], 0.0f);
#pragma unroll 2
        for (int ks = 0; ks < 16; ks++) {
            wmma::fragment<wmma::matrix_a, 16, 16, 16, __nv_bfloat16, wmma::row_major> af;
            wmma::load_matrix_sync(af, a_bf + wid * 16 * ALD + ks * 16, ALD);
#pragma unroll
            for (int nt = 0; nt < 5; nt++) {
                wmma::fragment<wmma::matrix_b, 16, 16, 16, __nv_bfloat16, wmma::col_major> bf;
                wmma::load_matrix_sync(bf, b1s + nt * 16 * 256 + ks * 16, 256);
                wmma::mma_sync(acc1[nt], af, bf, acc1[nt]);
            }
        }
    }
    __syncthreads();   // A dead; accumulators in regs
    if (wid < 13) {
#pragma unroll
        for (int nt = 0; nt < 5; nt++)
            wmma::store_matrix_sync(d1f + wid * 16 * D1 + nt * 16, acc1[nt], D1,
                                    wmma::mem_row_major);
    }
    __syncthreads();

    // ---- epilogue 1: S1 = sigf(D1 + cq) bf16 ----
    for (int i = tid; i < TPH * D1; i += 512) {
        int j = i % D1;
        s1p[i] = __float2bfloat16(sigf(d1f[i] + cqs[j]));
    }
    __syncthreads();

    // ---- layer 2: D2[208x48] = S1[208x80] @ B2^T (bf16 wmma) ----
    if (wid < 13) {
        wmma::fragment<wmma::accumulator, 16, 16, 16, float> acc2[3];
#pragma unroll
        for (int nt = 0; nt < 3; nt++) wmma::fill_fragment(acc2[nt], 0.0f);
#pragma unroll
        for (int ks = 0; ks < 5; ks++) {
            wmma::fragment<wmma::matrix_a, 16, 16, 16, __nv_bfloat16, wmma::row_major> af;
            wmma::load_matrix_sync(af, s1p + wid * 16 * D1 + ks * 16, D1);
#pragma unroll
            for (int nt = 0; nt < 3; nt++) {
                wmma::fragment<wmma::matrix_b, 16, 16, 16, __nv_bfloat16, wmma::col_major> bf;
                wmma::load_matrix_sync(bf, b2s + nt * 16 * D1 + ks * 16, D1);
                wmma::mma_sync(acc2[nt], af, bf, acc2[nt]);
            }
        }
#pragma unroll
        for (int nt = 0; nt < 3; nt++)
            wmma::store_matrix_sync(d2f + wid * 16 * 52 + nt * 16, acc2[nt], 52,
                                    wmma::mem_row_major);
    }
    __syncthreads();

    // ---- layer 3 + score ----
    float sc = -FLT_MAX;
    if (tid < TT) {
        if (tid < len) {
            float score = b3[0];
            const float* dr = d2f + tid * 52;
#pragma unroll
            for (int n = 0; n < D2; n++)
                score = fmaf(sigf(dr[n] + b2v[n]), w3s[n], score);
            sc = score * RSQRT_K;
        } else {
            sc = MASKV * RSQRT_K;
        }
    }

    // ---- softmax (512-wide) ----
    red[tid] = sc;
    __syncthreads();
#pragma unroll
    for (int s = 256; s > 0; s >>= 1) {
        if (tid < s) red[tid] = fmaxf(red[tid], red[tid + s]);
        __syncthreads();
    }
    const float mx = red[0];
    __syncthreads();
    float p = 0.0f;
    if (tid < TT) p = __expf(sc - mx);
    red[tid] = p;
    __syncthreads();
#pragma unroll
    for (int s = 256; s > 0; s >>= 1) {
        if (tid < s) red[tid] += red[tid + s];
        __syncthreads();
    }
    if (tid < TT) g_attn[b * 224 + tid] = p * (1.0f / red[0]);
}

// =====================================================================
// ATT-B: hist_attn[b][k] = sum_t attn[t] * hist_join[t][k]  (fp32 exact)
// grid BB, 256 threads
// =====================================================================
__global__ __launch_bounds__(256) void attnbag_kernel(
    const int* __restrict__ history, const int* __restrict__ length,
    const int* __restrict__ cate_list,
    const float* __restrict__ item_table, const float* __restrict__ cate_table)
{
    __shared__ float part[8][128];
    const int b = blockIdx.x;
    const int tid = threadIdx.x;
    const int lane = tid & 31, w = tid >> 5;
    const int len = length[b];

    float4 acc = make_float4(0.f, 0.f, 0.f, 0.f);
    for (int t = w; t < len; t += 8) {
        float a = g_attn[b * 224 + t];
        int hidx = history[b * TT + t];
        const float4* row = (lane < 16)
            ? (const float4*)(item_table + (size_t)hidx * 64) + lane
            : (const float4*)(cate_table + (size_t)cate_list[hidx] * 64) + (lane - 16);
        float4 v = *row;
        acc.x = fmaf(a, v.x, acc.x);
        acc.y = fmaf(a, v.y, acc.y);
        acc.z = fmaf(a, v.z, acc.z);
        acc.w = fmaf(a, v.w, acc.w);
    }
    ((float4*)part[w])[lane] = acc;
    __syncthreads();
    if (tid < 128) {
        float s = 0.f;
#pragma unroll
        for (int i = 0; i < 8; i++) s += part[i][tid];
        g_hist_attn[b * KK + tid] = s;
    }
}

// =====================================================================
// final: dice + fc3 + item bias + sigmoid
// =====================================================================
__global__ void final_k(const float* __restrict__ W3, const float* __restrict__ b3,
                        const float* __restrict__ alpha, const float* __restrict__ beta,
                        float* __restrict__ out, int out_size)
{
    int b = blockIdx.x * blockDim.x + threadIdx.x;
    if (b >= BB) return;
    float acc = b3[0];
#pragma unroll
    for (int k = 0; k < D2; k++) {
        float v  = g_y2[b * D2 + k];
        float xn = (v - g_m4[k]) * g_r4[k];
        float pp = sigf(beta[k] * xn);
        v = v * (pp + alpha[k] * (1.0f - pp));
        acc = fmaf(v, W3[k], acc);
    }
    acc += g_obias[b];
    if (b < out_size) out[b] = acc;
    if (BB + b < out_size) out[BB + b] = sigf_precise(acc);
}

// =====================================================================
// launch
// =====================================================================
extern "C" void kernel_launch(void* const* d_in, const int* in_sizes, int n_in,
                              void* d_out, int out_size)
{
    const int*   user       = (const int*)  d_in[0];
    const int*   item       = (const int*)  d_in[1];
    const int*   history    = (const int*)  d_in[2];
    const int*   length     = (const int*)  d_in[3];
    const int*   cate_list  = (const int*)  d_in[4];
    const float* user_table = (const float*)d_in[5];
    const float* item_table = (const float*)d_in[6];
    const float* cate_table = (const float*)d_in[7];
    const float* item_bias  = (const float*)d_in[8];
    const float* att_W1     = (const float*)d_in[9];
    const float* att_b1     = (const float*)d_in[10];
    const float* att_W2     = (const float*)d_in[11];
    const float* att_b2     = (const float*)d_in[12];
    const float* att_W3     = (const float*)d_in[13];
    const float* att_b3     = (const float*)d_in[14];
    const float* hbn_gamma  = (const float*)d_in[15];
    const float* hbn_beta   = (const float*)d_in[16];
    const float* hist_W     = (const float*)d_in[17];
    const float* hist_b     = (const float*)d_in[18];
    const float* fbn_gamma  = (const float*)d_in[19];
    const float* fbn_beta   = (const float*)d_in[20];
    const float* fc1_W      = (const float*)d_in[21];
    const float* fc1_b      = (const float*)d_in[22];
    const float* d1_alpha   = (const float*)d_in[23];
    const float* d1_beta    = (const float*)d_in[24];
    const float* fc2_W      = (const float*)d_in[25];
    const float* fc2_b      = (const float*)d_in[26];
    const float* d2_alpha   = (const float*)d_in[27];
    const float* d2_beta    = (const float*)d_in[28];
    const float* fc3_W      = (const float*)d_in[29];
    const float* fc3_b      = (const float*)d_in[30];
    float* out = (float*)d_out;

    float *p_q, *p_cq, *p_wac, *p_ha, *p_join, *p_y1, *p_y2;
    float *p_m1, *p_r1, *p_m2, *p_r2, *p_m3, *p_r3, *p_m4, *p_r4;
    cudaGetSymbolAddress((void**)&p_q,    g_q);
    cudaGetSymbolAddress((void**)&p_cq,   g_cq);
    cudaGetSymbolAddress((void**)&p_wac,  g_Wac);
    cudaGetSymbolAddress((void**)&p_ha,   g_hist_attn);
    cudaGetSymbolAddress((void**)&p_join, g_join);
    cudaGetSymbolAddress((void**)&p_y1,   g_y1);
    cudaGetSymbolAddress((void**)&p_y2,   g_y2);
    cudaGetSymbolAddress((void**)&p_m1,   g_m1);
    cudaGetSymbolAddress((void**)&p_r1,   g_r1);
    cudaGetSymbolAddress((void**)&p_m2,   g_m2);
    cudaGetSymbolAddress((void**)&p_r2,   g_r2);
    cudaGetSymbolAddress((void**)&p_m3,   g_m3);
    cudaGetSymbolAddress((void**)&p_r3,   g_r3);
    cudaGetSymbolAddress((void**)&p_m4,   g_m4);
    cudaGetSymbolAddress((void**)&p_r4,   g_r4);

    cudaFuncSetAttribute(att_kernel, cudaFuncAttributeMaxDynamicSharedMemorySize,
                         SMEM_ATT_TOTAL);

    auto smemG = [](int KIN, int JOUT) { return (JOUT + 18) * (KIN + 2) * 4; };
    cudaFuncSetAttribute((const void*)gemm_smemW<128, 80, 0>,
        cudaFuncAttributeMaxDynamicSharedMemorySize, smemG(128, 80));
    cudaFuncSetAttribute((const void*)gemm_smemW<128, 128, 1>,
        cudaFuncAttributeMaxDynamicSharedMemorySize, smemG(128, 128));
    cudaFuncSetAttribute((const void*)gemm_smemW<384, 80, 1>,
        cudaFuncAttributeMaxDynamicSharedMemorySize, smemG(384, 80));
    cudaFuncSetAttribute((const void*)gemm_smemW<80, 40, 2>,
        cudaFuncAttributeMaxDynamicSharedMemorySize, smemG(80, 40));

    // 1-3: prep (att lands in profile slot 4)
    fold_W<<<95, 256>>>(att_W1, att_W2);
    prep_batch<<<BB, 128>>>(user, item, cate_list, user_table, item_table,
                            cate_table, item_bias);
    gemm_smemW<128, 80, 0><<<BB / 16, 256, smemG(128, 80)>>>(
        p_q, KK, p_wac, att_b1, p_cq, D1, 0, nullptr, nullptr, nullptr, nullptr);

    // 4: ATT-A (scores + softmax, bf16 wmma)
    att_kernel<<<BB, 512, SMEM_ATT_TOTAL>>>(history, length, cate_list,
                                            item_table, cate_table,
                                            att_b2, att_W3, att_b3);
    // 5: ATT-B (exact fp32 weighted embedding bag)
    attnbag_kernel<<<BB, 256>>>(history, length, cate_list, item_table, cate_table);

    // tail
    colstats2<<<(KK + 31) / 32, 512>>>(p_ha, BB, KK, p_m1, p_r1);
    gemm_smemW<128, 128, 1><<<BB / 16, 256, smemG(128, 128)>>>(
        p_ha, KK, hist_W, hist_b, p_join, DJ, 256, p_m1, p_r1, hbn_gamma, hbn_beta);
    colstats2<<<(DJ + 31) / 32, 512>>>(p_join, BB, DJ, p_m2, p_r2);
    gemm_smemW<384, 80, 1><<<BB / 16, 256, smemG(384, 80)>>>(
        p_join, DJ, fc1_W, fc1_b, p_y1, D1, 0, p_m2, p_r2, fbn_gamma, fbn_beta);
    colstats2<<<(D1 + 31) / 32, 512>>>(p_y1, BB, D1, p_m3, p_r3);
    gemm_smemW<80, 40, 2><<<BB / 16, 256, smemG(80, 40)>>>(
        p_y1, D1, fc2_W, fc2_b, p_y2, D2, 0, p_m3, p_r3, d1_alpha, d1_beta);
    colstats2<<<(D2 + 31) / 32, 512>>>(p_y2, BB, D2, p_m4, p_r4);
    final_k<<<(BB + 255) / 256, 256>>>(fc3_W, fc3_b, d2_alpha, d2_beta, out, out_size);
}

// round 9
// speedup vs baseline: 1.7123x; 1.5901x over previous
#include <cuda_runtime.h>
#include <cuda_bf16.h>
#include <mma.h>
#include <math.h>
#include <float.h>

using namespace nvcuda;

// ---------------- problem constants ----------------
#define BB 2048
#define TT 200
#define KK 128
#define UD 128
#define D1 80
#define D2 40
#define DJ 384
#define TPH 208                  // padded t (13 m-tiles)
#define ALD 264                  // A ldm: 528B rows (16 mod 128 -> conflict-free)
#define B1LD 264                 // B1 ldm (same rule)
#define S1LD 88                  // S1/B2 ldm: 176B rows (48 mod 128)
#define D1LD 88                  // D1 fp32 ldm: 352B (96 mod 128)
#define D2LD 56                  // D2 fp32 ldm: 224B (96 mod 128)
#define BN_EPS 1e-3f
#define MASKV (-4294967295.0f)
#define RSQRT_K 0.08838834764831843f

// ---- ATT-A SMEM layout (bytes) ----
#define A_OFF    0                       // bf16 A [208][264] = 109824 ; D1/D2 fp32 overlay
#define B1S_OFF  109824                  // bf16 B1 [80][264] = 42240
#define S1_OFF   152064                  // bf16 S1 [208][88] = 36608
#define B2S_OFF  188672                  // bf16 B2 [48][88]  = 8448
#define MISC_OFF 197120                  // fp32: qs128 cqs80 w3s40 b2v40 red512 = 3200
#define SMEM_ATT_TOTAL 200320

// ---------------- scratch (device globals) ----------
__device__ float g_q[BB * KK];
__device__ float g_cq[BB * D1];
__device__ float g_Wac[KK * D1];
__device__ __nv_bfloat16 g_B1bf[D1 * 256];   // [n][k] k-contig: k<128 Wbc, k>=128 W1d
__device__ __nv_bfloat16 g_B2bf[48 * D1];    // [n][k] W2^T padded to 48 n
__device__ float g_attn[BB * 224];
__device__ float g_obias[BB];
__device__ float g_hist_attn[BB * KK];
__device__ float g_join[BB * DJ];
__device__ float g_y1[BB * D1];
__device__ float g_y2[BB * D2];
__device__ float g_m1[KK],  g_r1[KK];
__device__ float g_m2[DJ],  g_r2[DJ];
__device__ float g_m3[D1],  g_r3[D1];
__device__ float g_m4[D2],  g_r4[D2];

// ---------------- helpers ----------------
__device__ __forceinline__ unsigned long long pack2(float x, float y) {
    unsigned long long r;
    asm("mov.b64 %0, {%1, %2};" : "=l"(r) : "f"(x), "f"(y));
    return r;
}
__device__ __forceinline__ float2 unpack2(unsigned long long v) {
    float2 r;
    asm("mov.b64 {%0, %1}, %2;" : "=f"(r.x), "=f"(r.y) : "l"(v));
    return r;
}
__device__ __forceinline__ void fma2(unsigned long long& d, unsigned long long a,
                                     unsigned long long b) {
    asm("fma.rn.f32x2 %0, %1, %2, %0;" : "+l"(d) : "l"(a), "l"(b));
}
__device__ __forceinline__ float sigf(float x) {
    float t;
    asm("tanh.approx.f32 %0, %1;" : "=f"(t) : "f"(x * 0.5f));
    return fmaf(0.5f, t, 0.5f);
}
__device__ __forceinline__ float sigf_precise(float x) {
    return __fdividef(1.0f, 1.0f + __expf(-x));
}
__device__ __forceinline__ unsigned int bf16x2_of(float x, float y) {
    unsigned int r;
    asm("cvt.rn.bf16x2.f32 %0, %2, %1;" : "=r"(r) : "f"(x), "f"(y));
    return r;
}

// =====================================================================
// fold: g_Wac fp32 + fixed bf16 B1 [80][256] + B2 [48][80]
// =====================================================================
__global__ void fold_W(const float* __restrict__ W1, const float* __restrict__ W2) {
    int i = blockIdx.x * blockDim.x + threadIdx.x;
    if (i < KK * D1) {
        int k = i / D1, n = i - k * D1;
        g_Wac[i] = W1[(size_t)k * D1 + n] + W1[(size_t)(2 * KK + k) * D1 + n];
    }
    if (i < D1 * 256) {
        int n = i >> 8, k = i & 255;
        float w;
        if (k < 128)
            w = W1[(size_t)(KK + k) * D1 + n] - W1[(size_t)(2 * KK + k) * D1 + n];
        else
            w = W1[(size_t)(3 * KK + (k - 128)) * D1 + n];
        g_B1bf[i] = __float2bfloat16(w);
    }
    int j = i - D1 * 256;
    if (j >= 0 && j < 48 * D1) {
        int n = j / D1, k = j - n * D1;
        g_B2bf[j] = (n < D2) ? __float2bfloat16(W2[(size_t)k * D2 + n])
                             : __float2bfloat16(0.0f);
    }
}

__global__ void prep_batch(const int* __restrict__ user, const int* __restrict__ item,
                           const int* __restrict__ cate_list,
                           const float* __restrict__ user_table,
                           const float* __restrict__ item_table,
                           const float* __restrict__ cate_table,
                           const float* __restrict__ item_bias) {
    int b = blockIdx.x, tid = threadIdx.x;
    int it = item[b];
    float qv = (tid < 64) ? item_table[(size_t)it * 64 + tid]
                          : cate_table[(size_t)cate_list[it] * 64 + (tid - 64)];
    g_q[b * KK + tid] = qv;
    g_join[b * DJ + UD + tid] = qv;
    g_join[b * DJ + tid] = user_table[(size_t)user[b] * UD + tid];
    if (tid == 0) g_obias[b] = item_bias[it];
}

// =====================================================================
// SMEM-staged tail GEMM (proven R4)
// =====================================================================
template<int KIN, int JOUT, int MODE>
__global__ __launch_bounds__(256) void gemm_smemW(
    const float* __restrict__ in, int in_stride,
    const float* __restrict__ W, const float* __restrict__ bias,
    float* __restrict__ out, int out_stride, int out_off,
    const float* __restrict__ mean, const float* __restrict__ rstd,
    const float* __restrict__ p1, const float* __restrict__ p2)
{
    constexpr int KP  = KIN + 2;
    constexpr int NR  = 256 / JOUT;
    constexpr int ACT = NR * JOUT;
    constexpr int M   = (16 + NR - 1) / NR;
    extern __shared__ float smg[];
    float* ws = smg;
    float* xs = ws + JOUT * KP;
    const int b0 = blockIdx.x * 16;

    for (int i = threadIdx.x; i < KIN * JOUT; i += 256) {
        int k = i / JOUT, j = i - k * JOUT;
        ws[j * KP + k] = W[i];
    }
    for (int i = threadIdx.x; i < 16 * KIN; i += 256) {
        int r = i / KIN, k = i - r * KIN;
        float v = in[(size_t)(b0 + r) * in_stride + k];
        if constexpr (MODE == 1) {
            v = (v - mean[k]) * rstd[k] * p1[k] + p2[k];
        } else if constexpr (MODE == 2) {
            float xn = (v - mean[k]) * rstd[k];
            float pp = sigf(p2[k] * xn);
            v = v * (pp + p1[k] * (1.0f - pp));
        }
        xs[r * KP + k] = v;
    }
    __syncthreads();

    if (threadIdx.x < ACT) {
        const int j  = threadIdx.x % JOUT;
        const int rg = threadIdx.x / JOUT;
        const float bj = bias[j];
        unsigned long long acc[M];
        const unsigned long long* xpr[M];
#pragma unroll
        for (int m = 0; m < M; m++) {
            acc[m] = 0ULL;
            xpr[m] = (const unsigned long long*)(xs + (rg + NR * m) * KP);
        }
        const unsigned long long* wp = (const unsigned long long*)(ws + j * KP);
#pragma unroll 4
        for (int kp = 0; kp < KIN / 2; kp++) {
            unsigned long long w2 = wp[kp];
#pragma unroll
            for (int m = 0; m < M; m++)
                fma2(acc[m], xpr[m][kp], w2);
        }
#pragma unroll
        for (int m = 0; m < M; m++) {
            int r = rg + NR * m;
            if (r < 16) {
                float2 v = unpack2(acc[m]);
                out[(size_t)(b0 + r) * out_stride + out_off + j] = v.x + v.y + bj;
            }
        }
    }
}

__global__ void colstats2(const float* __restrict__ x, int rows, int cols,
                          float* __restrict__ mean, float* __restrict__ rstd)
{
    __shared__ float ss[16][33], sq[16][33];
    int tx = threadIdx.x & 31, ty = threadIdx.x >> 5;
    int col = blockIdx.x * 32 + tx;
    float s = 0.f, q = 0.f;
    if (col < cols) {
#pragma unroll 8
        for (int r = ty; r < rows; r += 16) {
            float v = x[(size_t)r * cols + col];
            s += v; q = fmaf(v, v, q);
        }
    }
    ss[ty][tx] = s; sq[ty][tx] = q;
    __syncthreads();
    if (ty == 0 && col < cols) {
        float S = 0.f, Q = 0.f;
#pragma unroll
        for (int i = 0; i < 16; i++) { S += ss[i][tx]; Q += sq[i][tx]; }
        float m = S / (float)rows;
        float v = Q / (float)rows - m * m;
        mean[col] = m;
        rstd[col] = rsqrtf(v + BN_EPS);
    }
}

// =====================================================================
// ATT-A: per-batch scores + softmax. bf16 wmma, conflict-free padding.
// =====================================================================
__global__ __launch_bounds__(512, 1) void att_kernel(
    const int* __restrict__ history, const int* __restrict__ length,
    const int* __restrict__ cate_list,
    const float* __restrict__ item_table, const float* __restrict__ cate_table,
    const float* __restrict__ b2, const float* __restrict__ W3,
    const float* __restrict__ b3)
{
    extern __shared__ __align__(16) char smc[];
    __nv_bfloat16* a_bf = (__nv_bfloat16*)(smc + A_OFF);    // [208][264]
    float*         d1f  = (float*)(smc + A_OFF);            // overlay [208][88] fp32
    float*         d2f  = (float*)(smc + A_OFF);            // overlay [208][56] fp32
    __nv_bfloat16* b1s  = (__nv_bfloat16*)(smc + B1S_OFF);  // [80][264]
    __nv_bfloat16* s1p  = (__nv_bfloat16*)(smc + S1_OFF);   // [208][88]
    __nv_bfloat16* b2s  = (__nv_bfloat16*)(smc + B2S_OFF);  // [48][88]
    float* qs  = (float*)(smc + MISC_OFF);                  // 128
    float* cqs = qs + 128;                                  // 80
    float* w3s = cqs + 80;                                  // 40
    float* b2v = w3s + 40;                                  // 40
    float* red = b2v + 40;                                  // 512

    const int b   = blockIdx.x;
    const int tid = threadIdx.x;
    const int wid = tid >> 5;
    const int len = length[b];

    // ---- phase 0: stage small params, zero A ----
    if (tid < KK) qs[tid] = g_q[b * KK + tid];
    else if (tid < KK + D1) cqs[tid - KK] = g_cq[b * D1 + (tid - KK)];
    else if (tid < KK + D1 + D2) w3s[tid - KK - D1] = W3[tid - KK - D1];
    else if (tid < KK + D1 + 2 * D2) b2v[tid - KK - D1 - D2] = b2[tid - KK - D1 - D2];
    {
        uint4 z = make_uint4(0, 0, 0, 0);
        uint4* ap = (uint4*)a_bf;
        for (int i = tid; i < (TPH * ALD * 2) / 16; i += 512) ap[i] = z;
    }
    // stage B1 (re-strided 256 -> 264) and B2 (80 -> 88)
    for (int i = tid; i < D1 * 32; i += 512) {          // 32 uint4 chunks of 8 bf16 per row
        int n = i >> 5, c8 = (i & 31) << 3;             // k base
        *(uint4*)(b1s + n * B1LD + c8) = *(const uint4*)(g_B1bf + n * 256 + c8);
    }
    for (int i = tid; i < 48 * 10; i += 512) {          // 10 chunks of 8 per row
        int n = i / 10, c8 = (i % 10) << 3;
        *(uint4*)(b2s + n * S1LD + c8) = *(const uint4*)(g_B2bf + n * D1 + c8);
    }
    __syncthreads();

    // ---- gather + A build: thread (t, half) ----
    {
        int t = tid >> 1, half = tid & 1;
        if (t < len) {
            int hidx = history[b * TT + t];
            const float4* row = half
                ? (const float4*)(cate_table + (size_t)cate_list[hidx] * 64)
                : (const float4*)(item_table + (size_t)hidx * 64);
            int kb0 = half * 64;
            __nv_bfloat16* arow = a_bf + t * ALD;
#pragma unroll
            for (int c = 0; c < 16; c++) {
                float4 v = row[c];
                int k = kb0 + 4 * c;
                *(unsigned int*)(arow + k)     = bf16x2_of(v.x, v.y);
                *(unsigned int*)(arow + k + 2) = bf16x2_of(v.z, v.w);
                *(unsigned int*)(arow + 128 + k)     = bf16x2_of(qs[k] * v.x, qs[k + 1] * v.y);
                *(unsigned int*)(arow + 128 + k + 2) = bf16x2_of(qs[k + 2] * v.z, qs[k + 3] * v.w);
            }
        }
    }
    __syncthreads();

    // ---- layer 1: D1[208x80] = A[208x256] @ B1^T  (bf16 wmma) ----
    wmma::fragment<wmma::accumulator, 16, 16, 16, float> acc1[5];
    if (wid < 13) {
#pragma unroll
        for (int nt = 0; nt < 5; nt++) wmma::fill_fragment(acc1[nt], 0.0f);
#pragma unroll 2
        for (int ks = 0; ks < 16; ks++) {
            wmma::fragment<wmma::matrix_a, 16, 16, 16, __nv_bfloat16, wmma::row_major> af;
            wmma::load_matrix_sync(af, a_bf + wid * 16 * ALD + ks * 16, ALD);
#pragma unroll
            for (int nt = 0; nt < 5; nt++) {
                wmma::fragment<wmma::matrix_b, 16, 16, 16, __nv_bfloat16, wmma::col_major> bf;
                wmma::load_matrix_sync(bf, b1s + nt * 16 * B1LD + ks * 16, B1LD);
                wmma::mma_sync(acc1[nt], af, bf, acc1[nt]);
            }
        }
    }
    __syncthreads();   // A dead; accumulators live in regs
    if (wid < 13) {
#pragma unroll
        for (int nt = 0; nt < 5; nt++)
            wmma::store_matrix_sync(d1f + wid * 16 * D1LD + nt * 16, acc1[nt], D1LD,
                                    wmma::mem_row_major);
    }
    __syncthreads();

    // ---- epilogue 1: S1 = sigf(D1 + cq) bf16 ----
    for (int i = tid; i < TPH * D1; i += 512) {
        int t = i / D1, j = i - t * D1;
        s1p[t * S1LD + j] = __float2bfloat16(sigf(d1f[t * D1LD + j] + cqs[j]));
    }
    __syncthreads();

    // ---- layer 2: D2[208x48] = S1[208x80] @ B2^T (bf16 wmma) ----
    if (wid < 13) {
        wmma::fragment<wmma::accumulator, 16, 16, 16, float> acc2[3];
#pragma unroll
        for (int nt = 0; nt < 3; nt++) wmma::fill_fragment(acc2[nt], 0.0f);
#pragma unroll
        for (int ks = 0; ks < 5; ks++) {
            wmma::fragment<wmma::matrix_a, 16, 16, 16, __nv_bfloat16, wmma::row_major> af;
            wmma::load_matrix_sync(af, s1p + wid * 16 * S1LD + ks * 16, S1LD);
#pragma unroll
            for (int nt = 0; nt < 3; nt++) {
                wmma::fragment<wmma::matrix_b, 16, 16, 16, __nv_bfloat16, wmma::col_major> bf;
                wmma::load_matrix_sync(bf, b2s + nt * 16 * S1LD + ks * 16, S1LD);
                wmma::mma_sync(acc2[nt], af, bf, acc2[nt]);
            }
        }
#pragma unroll
        for (int nt = 0; nt < 3; nt++)
            wmma::store_matrix_sync(d2f + wid * 16 * D2LD + nt * 16, acc2[nt], D2LD,
                                    wmma::mem_row_major);
    }
    __syncthreads();

    // ---- layer 3 + score ----
    float sc = -FLT_MAX;
    if (tid < TT) {
        if (tid < len) {
            float score = b3[0];
            const float* dr = d2f + tid * D2LD;
#pragma unroll
            for (int n = 0; n < D2; n++)
                score = fmaf(sigf(dr[n] + b2v[n]), w3s[n], score);
            sc = score * RSQRT_K;
        } else {
            sc = MASKV * RSQRT_K;
        }
    }

    // ---- softmax (512-wide) ----
    red[tid] = sc;
    __syncthreads();
#pragma unroll
    for (int s = 256; s > 0; s >>= 1) {
        if (tid < s) red[tid] = fmaxf(red[tid], red[tid + s]);
        __syncthreads();
    }
    const float mx = red[0];
    __syncthreads();
    float p = 0.0f;
    if (tid < TT) p = __expf(sc - mx);
    red[tid] = p;
    __syncthreads();
#pragma unroll
    for (int s = 256; s > 0; s >>= 1) {
        if (tid < s) red[tid] += red[tid + s];
        __syncthreads();
    }
    if (tid < TT) g_attn[b * 224 + tid] = p * (1.0f / red[0]);
}

// =====================================================================
// ATT-B: hist_attn[b][k] = sum_t attn[t] * hist_join[t][k]  (fp32 exact)
// =====================================================================
__global__ __launch_bounds__(256) void attnbag_kernel(
    const int* __restrict__ history, const int* __restrict__ length,
    const int* __restrict__ cate_list,
    const float* __restrict__ item_table, const float* __restrict__ cate_table)
{
    __shared__ float part[8][128];
    const int b = blockIdx.x;
    const int tid = threadIdx.x;
    const int lane = tid & 31, w = tid >> 5;
    const int len = length[b];

    float4 acc = make_float4(0.f, 0.f, 0.f, 0.f);
    for (int t = w; t < len; t += 8) {
        float a = g_attn[b * 224 + t];
        int hidx = history[b * TT + t];
        const float4* row = (lane < 16)
            ? (const float4*)(item_table + (size_t)hidx * 64) + lane
            : (const float4*)(cate_table + (size_t)cate_list[hidx] * 64) + (lane - 16);
        float4 v = *row;
        acc.x = fmaf(a, v.x, acc.x);
        acc.y = fmaf(a, v.y, acc.y);
        acc.z = fmaf(a, v.z, acc.z);
        acc.w = fmaf(a, v.w, acc.w);
    }
    ((float4*)part[w])[lane] = acc;
    __syncthreads();
    if (tid < 128) {
        float s = 0.f;
#pragma unroll
        for (int i = 0; i < 8; i++) s += part[i][tid];
        g_hist_attn[b * KK + tid] = s;
    }
}

// =====================================================================
// final: dice + fc3 + item bias + sigmoid
// =====================================================================
__global__ void final_k(const float* __restrict__ W3, const float* __restrict__ b3,
                        const float* __restrict__ alpha, const float* __restrict__ beta,
                        float* __restrict__ out, int out_size)
{
    int b = blockIdx.x * blockDim.x + threadIdx.x;
    if (b >= BB) return;
    float acc = b3[0];
#pragma unroll
    for (int k = 0; k < D2; k++) {
        float v  = g_y2[b * D2 + k];
        float xn = (v - g_m4[k]) * g_r4[k];
        float pp = sigf(beta[k] * xn);
        v = v * (pp + alpha[k] * (1.0f - pp));
        acc = fmaf(v, W3[k], acc);
    }
    acc += g_obias[b];
    if (b < out_size) out[b] = acc;
    if (BB + b < out_size) out[BB + b] = sigf_precise(acc);
}

// =====================================================================
// launch
// =====================================================================
extern "C" void kernel_launch(void* const* d_in, const int* in_sizes, int n_in,
                              void* d_out, int out_size)
{
    const int*   user       = (const int*)  d_in[0];
    const int*   item       = (const int*)  d_in[1];
    const int*   history    = (const int*)  d_in[2];
    const int*   length     = (const int*)  d_in[3];
    const int*   cate_list  = (const int*)  d_in[4];
    const float* user_table = (const float*)d_in[5];
    const float* item_table = (const float*)d_in[6];
    const float* cate_table = (const float*)d_in[7];
    const float* item_bias  = (const float*)d_in[8];
    const float* att_W1     = (const float*)d_in[9];
    const float* att_b1     = (const float*)d_in[10];
    const float* att_W2     = (const float*)d_in[11];
    const float* att_b2     = (const float*)d_in[12];
    const float* att_W3     = (const float*)d_in[13];
    const float* att_b3     = (const float*)d_in[14];
    const float* hbn_gamma  = (const float*)d_in[15];
    const float* hbn_beta   = (const float*)d_in[16];
    const float* hist_W     = (const float*)d_in[17];
    const float* hist_b     = (const float*)d_in[18];
    const float* fbn_gamma  = (const float*)d_in[19];
    const float* fbn_beta   = (const float*)d_in[20];
    const float* fc1_W      = (const float*)d_in[21];
    const float* fc1_b      = (const float*)d_in[22];
    const float* d1_alpha   = (const float*)d_in[23];
    const float* d1_beta    = (const float*)d_in[24];
    const float* fc2_W      = (const float*)d_in[25];
    const float* fc2_b      = (const float*)d_in[26];
    const float* d2_alpha   = (const float*)d_in[27];
    const float* d2_beta    = (const float*)d_in[28];
    const float* fc3_W      = (const float*)d_in[29];
    const float* fc3_b      = (const float*)d_in[30];
    float* out = (float*)d_out;

    float *p_q, *p_cq, *p_wac, *p_ha, *p_join, *p_y1, *p_y2;
    float *p_m1, *p_r1, *p_m2, *p_r2, *p_m3, *p_r3, *p_m4, *p_r4;
    cudaGetSymbolAddress((void**)&p_q,    g_q);
    cudaGetSymbolAddress((void**)&p_cq,   g_cq);
    cudaGetSymbolAddress((void**)&p_wac,  g_Wac);
    cudaGetSymbolAddress((void**)&p_ha,   g_hist_attn);
    cudaGetSymbolAddress((void**)&p_join, g_join);
    cudaGetSymbolAddress((void**)&p_y1,   g_y1);
    cudaGetSymbolAddress((void**)&p_y2,   g_y2);
    cudaGetSymbolAddress((void**)&p_m1,   g_m1);
    cudaGetSymbolAddress((void**)&p_r1,   g_r1);
    cudaGetSymbolAddress((void**)&p_m2,   g_m2);
    cudaGetSymbolAddress((void**)&p_r2,   g_r2);
    cudaGetSymbolAddress((void**)&p_m3,   g_m3);
    cudaGetSymbolAddress((void**)&p_r3,   g_r3);
    cudaGetSymbolAddress((void**)&p_m4,   g_m4);
    cudaGetSymbolAddress((void**)&p_r4,   g_r4);

    cudaFuncSetAttribute(att_kernel, cudaFuncAttributeMaxDynamicSharedMemorySize,
                         SMEM_ATT_TOTAL);

    auto smemG = [](int KIN, int JOUT) { return (JOUT + 18) * (KIN + 2) * 4; };
    cudaFuncSetAttribute((const void*)gemm_smemW<128, 80, 0>,
        cudaFuncAttributeMaxDynamicSharedMemorySize, smemG(128, 80));
    cudaFuncSetAttribute((const void*)gemm_smemW<128, 128, 1>,
        cudaFuncAttributeMaxDynamicSharedMemorySize, smemG(128, 128));
    cudaFuncSetAttribute((const void*)gemm_smemW<384, 80, 1>,
        cudaFuncAttributeMaxDynamicSharedMemorySize, smemG(384, 80));
    cudaFuncSetAttribute((const void*)gemm_smemW<80, 40, 2>,
        cudaFuncAttributeMaxDynamicSharedMemorySize, smemG(80, 40));

    // 1-3: prep (att lands in profile slot 4)
    fold_W<<<95, 256>>>(att_W1, att_W2);
    prep_batch<<<BB, 128>>>(user, item, cate_list, user_table, item_table,
                            cate_table, item_bias);
    gemm_smemW<128, 80, 0><<<BB / 16, 256, smemG(128, 80)>>>(
        p_q, KK, p_wac, att_b1, p_cq, D1, 0, nullptr, nullptr, nullptr, nullptr);

    // 4: ATT-A (scores + softmax, bf16 wmma, conflict-free)
    att_kernel<<<BB, 512, SMEM_ATT_TOTAL>>>(history, length, cate_list,
                                            item_table, cate_table,
                                            att_b2, att_W3, att_b3);
    // 5: ATT-B (exact fp32 weighted embedding bag)
    attnbag_kernel<<<BB, 256>>>(history, length, cate_list, item_table, cate_table);

    // tail
    colstats2<<<(KK + 31) / 32, 512>>>(p_ha, BB, KK, p_m1, p_r1);
    gemm_smemW<128, 128, 1><<<BB / 16, 256, smemG(128, 128)>>>(
        p_ha, KK, hist_W, hist_b, p_join, DJ, 256, p_m1, p_r1, hbn_gamma, hbn_beta);
    colstats2<<<(DJ + 31) / 32, 512>>>(p_join, BB, DJ, p_m2, p_r2);
    gemm_smemW<384, 80, 1><<<BB / 16, 256, smemG(384, 80)>>>(
        p_join, DJ, fc1_W, fc1_b, p_y1, D1, 0, p_m2, p_r2, fbn_gamma, fbn_beta);
    colstats2<<<(D1 + 31) / 32, 512>>>(p_y1, BB, D1, p_m3, p_r3);
    gemm_smemW<80, 40, 2><<<BB / 16, 256, smemG(80, 40)>>>(
        p_y1, D1, fc2_W, fc2_b, p_y2, D2, 0, p_m3, p_r3, d1_alpha, d1_beta);
    colstats2<<<(D2 + 31) / 32, 512>>>(p_y2, BB, D2, p_m4, p_r4);
    final_k<<<(BB + 255) / 256, 256>>>(fc3_W, fc3_b, d2_alpha, d2_beta, out, out_size);
}

// round 10
// speedup vs baseline: 1.8837x; 1.1001x over previous
#include <cuda_runtime.h>
#include <cuda_bf16.h>
#include <mma.h>
#include <math.h>
#include <float.h>

using namespace nvcuda;

// ---------------- problem constants ----------------
#define BB 2048
#define TT 200
#define KK 128
#define UD 128
#define D1 80
#define D2 40
#define DJ 384
#define TH 104                   // t per half-CTA
#define THP 112                  // padded (7 m-tiles)
#define ALD2 136                 // A ldm: 272B rows (16 mod 128 -> conflict-free)
#define S1LD 88                  // 176B (48 mod 128)
#define D1LD 88
#define D2LD 56
#define BN_EPS 1e-3f
#define MASKV (-4294967295.0f)
#define RSQRT_K 0.08838834764831843f

// ---- ATT-A SMEM layout (bytes) per half-CTA ----
#define A_OFF    0                       // bf16 A [112][136] = 30464 ; D1/D2 fp32 overlay
#define B1S_OFF  30464                   // bf16 weff [80][136] = 21760  (A+B1 = 52224 >= D1 39424)
#define S1_OFF   52224                   // bf16 S1 [112][88] = 19712
#define B2S_OFF  71936                   // bf16 B2 [48][88]  = 8448
#define MISC_OFF 80384                   // fp32: qs128 cqs80 w3s40 b2v40 = 1152
#define SMEM_ATT_TOTAL 81536

// ---------------- scratch (device globals) ----------
__device__ float g_q[BB * KK];
__device__ float g_cq[BB * D1];
__device__ float g_Wac[KK * D1];
__device__ float g_Wbc[KK * D1];             // fp32 [k][j] = W1b - W1c
__device__ __nv_bfloat16 g_B2bf[48 * D1];    // [n][k] W2^T padded to 48 n
__device__ float g_attn[BB * 224];           // raw masked scores from ATT-A
__device__ float g_obias[BB];
__device__ float g_hist_attn[BB * KK];
__device__ float g_join[BB * DJ];
__device__ float g_y1[BB * D1];
__device__ float g_y2[BB * D2];
__device__ float g_m1[KK],  g_r1[KK];
__device__ float g_m2[DJ],  g_r2[DJ];
__device__ float g_m3[D1],  g_r3[D1];
__device__ float g_m4[D2],  g_r4[D2];

// ---------------- helpers ----------------
__device__ __forceinline__ unsigned long long pack2(float x, float y) {
    unsigned long long r;
    asm("mov.b64 %0, {%1, %2};" : "=l"(r) : "f"(x), "f"(y));
    return r;
}
__device__ __forceinline__ float2 unpack2(unsigned long long v) {
    float2 r;
    asm("mov.b64 {%0, %1}, %2;" : "=f"(r.x), "=f"(r.y) : "l"(v));
    return r;
}
__device__ __forceinline__ void fma2(unsigned long long& d, unsigned long long a,
                                     unsigned long long b) {
    asm("fma.rn.f32x2 %0, %1, %2, %0;" : "+l"(d) : "l"(a), "l"(b));
}
__device__ __forceinline__ float sigf(float x) {
    float t;
    asm("tanh.approx.f32 %0, %1;" : "=f"(t) : "f"(x * 0.5f));
    return fmaf(0.5f, t, 0.5f);
}
__device__ __forceinline__ float sigf_precise(float x) {
    return __fdividef(1.0f, 1.0f + __expf(-x));
}
__device__ __forceinline__ unsigned int bf16x2_of(float x, float y) {
    unsigned int r;
    asm("cvt.rn.bf16x2.f32 %0, %2, %1;" : "=r"(r) : "f"(x), "f"(y));
    return r;
}

// =====================================================================
// fold: g_Wac, g_Wbc fp32 + fixed bf16 B2 [48][80]
// =====================================================================
__global__ void fold_W(const float* __restrict__ W1, const float* __restrict__ W2) {
    int i = blockIdx.x * blockDim.x + threadIdx.x;
    if (i < KK * D1) {
        int k = i / D1, n = i - k * D1;
        float a = W1[(size_t)k * D1 + n];
        float bw = W1[(size_t)(KK + k) * D1 + n];
        float c = W1[(size_t)(2 * KK + k) * D1 + n];
        g_Wac[i] = a + c;
        g_Wbc[i] = bw - c;
    }
    if (i < 48 * D1) {
        int n = i / D1, k = i - n * D1;
        g_B2bf[i] = (n < D2) ? __float2bfloat16(W2[(size_t)k * D2 + n])
                             : __float2bfloat16(0.0f);
    }
}

__global__ void prep_batch(const int* __restrict__ user, const int* __restrict__ item,
                           const int* __restrict__ cate_list,
                           const float* __restrict__ user_table,
                           const float* __restrict__ item_table,
                           const float* __restrict__ cate_table,
                           const float* __restrict__ item_bias) {
    int b = blockIdx.x, tid = threadIdx.x;
    int it = item[b];
    float qv = (tid < 64) ? item_table[(size_t)it * 64 + tid]
                          : cate_table[(size_t)cate_list[it] * 64 + (tid - 64)];
    g_q[b * KK + tid] = qv;
    g_join[b * DJ + UD + tid] = qv;
    g_join[b * DJ + tid] = user_table[(size_t)user[b] * UD + tid];
    if (tid == 0) g_obias[b] = item_bias[it];
}

// =====================================================================
// SMEM-staged tail GEMM (proven R4)
// =====================================================================
template<int KIN, int JOUT, int MODE>
__global__ __launch_bounds__(256) void gemm_smemW(
    const float* __restrict__ in, int in_stride,
    const float* __restrict__ W, const float* __restrict__ bias,
    float* __restrict__ out, int out_stride, int out_off,
    const float* __restrict__ mean, const float* __restrict__ rstd,
    const float* __restrict__ p1, const float* __restrict__ p2)
{
    constexpr int KP  = KIN + 2;
    constexpr int NR  = 256 / JOUT;
    constexpr int ACT = NR * JOUT;
    constexpr int M   = (16 + NR - 1) / NR;
    extern __shared__ float smg[];
    float* ws = smg;
    float* xs = ws + JOUT * KP;
    const int b0 = blockIdx.x * 16;

    for (int i = threadIdx.x; i < KIN * JOUT; i += 256) {
        int k = i / JOUT, j = i - k * JOUT;
        ws[j * KP + k] = W[i];
    }
    for (int i = threadIdx.x; i < 16 * KIN; i += 256) {
        int r = i / KIN, k = i - r * KIN;
        float v = in[(size_t)(b0 + r) * in_stride + k];
        if constexpr (MODE == 1) {
            v = (v - mean[k]) * rstd[k] * p1[k] + p2[k];
        } else if constexpr (MODE == 2) {
            float xn = (v - mean[k]) * rstd[k];
            float pp = sigf(p2[k] * xn);
            v = v * (pp + p1[k] * (1.0f - pp));
        }
        xs[r * KP + k] = v;
    }
    __syncthreads();

    if (threadIdx.x < ACT) {
        const int j  = threadIdx.x % JOUT;
        const int rg = threadIdx.x / JOUT;
        const float bj = bias[j];
        unsigned long long acc[M];
        const unsigned long long* xpr[M];
#pragma unroll
        for (int m = 0; m < M; m++) {
            acc[m] = 0ULL;
            xpr[m] = (const unsigned long long*)(xs + (rg + NR * m) * KP);
        }
        const unsigned long long* wp = (const unsigned long long*)(ws + j * KP);
#pragma unroll 4
        for (int kp = 0; kp < KIN / 2; kp++) {
            unsigned long long w2 = wp[kp];
#pragma unroll
            for (int m = 0; m < M; m++)
                fma2(acc[m], xpr[m][kp], w2);
        }
#pragma unroll
        for (int m = 0; m < M; m++) {
            int r = rg + NR * m;
            if (r < 16) {
                float2 v = unpack2(acc[m]);
                out[(size_t)(b0 + r) * out_stride + out_off + j] = v.x + v.y + bj;
            }
        }
    }
}

__global__ void colstats2(const float* __restrict__ x, int rows, int cols,
                          float* __restrict__ mean, float* __restrict__ rstd)
{
    __shared__ float ss[16][33], sq[16][33];
    int tx = threadIdx.x & 31, ty = threadIdx.x >> 5;
    int col = blockIdx.x * 32 + tx;
    float s = 0.f, q = 0.f;
    if (col < cols) {
#pragma unroll 8
        for (int r = ty; r < rows; r += 16) {
            float v = x[(size_t)r * cols + col];
            s += v; q = fmaf(v, v, q);
        }
    }
    ss[ty][tx] = s; sq[ty][tx] = q;
    __syncthreads();
    if (ty == 0 && col < cols) {
        float S = 0.f, Q = 0.f;
#pragma unroll
        for (int i = 0; i < 16; i++) { S += ss[i][tx]; Q += sq[i][tx]; }
        float m = S / (float)rows;
        float v = Q / (float)rows - m * m;
        mean[col] = m;
        rstd[col] = rsqrtf(v + BN_EPS);
    }
}

// =====================================================================
// ATT-A: raw scores for half a batch per CTA. bf16 wmma. grid = 2*BB.
// 256 threads, 81.5KB smem -> 2 CTAs/SM.
// =====================================================================
__global__ __launch_bounds__(256) void att_kernel(
    const int* __restrict__ history, const int* __restrict__ length,
    const int* __restrict__ cate_list,
    const float* __restrict__ item_table, const float* __restrict__ cate_table,
    const float* __restrict__ W1,
    const float* __restrict__ b2, const float* __restrict__ W3,
    const float* __restrict__ b3)
{
    extern __shared__ __align__(16) char smc[];
    __nv_bfloat16* a_bf = (__nv_bfloat16*)(smc + A_OFF);    // [112][136]
    float*         d1f  = (float*)(smc + A_OFF);            // overlay [112][88] fp32
    float*         d2f  = (float*)(smc + A_OFF);            // overlay [112][56] fp32
    __nv_bfloat16* b1s  = (__nv_bfloat16*)(smc + B1S_OFF);  // weff [80][136] (n-major)
    __nv_bfloat16* s1p  = (__nv_bfloat16*)(smc + S1_OFF);   // [112][88]
    __nv_bfloat16* b2s  = (__nv_bfloat16*)(smc + B2S_OFF);  // [48][88]
    float* qs  = (float*)(smc + MISC_OFF);                  // 128
    float* cqs = qs + 128;                                  // 80
    float* w3s = cqs + 80;                                  // 40
    float* b2v = w3s + 40;                                  // 40

    const int bx  = blockIdx.x;
    const int b   = bx >> 1;
    const int h0  = (bx & 1) * TH;          // global t offset of this half
    const int tid = threadIdx.x;
    const int wid = tid >> 5;
    const int len = length[b];

    // ---- stage small params ----
    if (tid < KK) qs[tid] = g_q[b * KK + tid];
    if (tid < D1) cqs[tid] = g_cq[b * D1 + tid];
    if (tid < D2) { w3s[tid] = W3[tid]; b2v[tid] = b2[tid]; }

    // zero A (bf16 [112][136] = 1904 uint4)
    {
        uint4 z = make_uint4(0, 0, 0, 0);
        uint4* ap = (uint4*)a_bf;
        for (int i = tid; i < (THP * ALD2 * 2) / 16; i += 256) ap[i] = z;
    }
    // stage B2 (80 -> 88 restride)
    for (int i = tid; i < 48 * 10; i += 256) {
        int n = i / 10, c8 = (i % 10) << 3;
        *(uint4*)(b2s + n * S1LD + c8) = *(const uint4*)(g_B2bf + n * D1 + c8);
    }
    __syncthreads();   // qs ready before weff build

    // ---- weff build: b1s[j][k] = Wbc[k][j] + q_k * W1d[k][j] ----
    for (int i = tid; i < KK * D1; i += 256) {
        int k = i / D1, j = i - k * D1;
        float w = fmaf(qs[k], W1[(size_t)(3 * KK + k) * D1 + j], g_Wbc[i]);
        b1s[j * ALD2 + k] = __float2bfloat16(w);
    }

    // ---- gather A = hist rows (t local, only t_g < len) ----
    {
        int t = tid >> 1, half = tid & 1;
        int tg = h0 + t;
        if (t < TH && tg < len) {
            int hidx = history[b * TT + tg];
            const float4* row = half
                ? (const float4*)(cate_table + (size_t)cate_list[hidx] * 64)
                : (const float4*)(item_table + (size_t)hidx * 64);
            int kb0 = half * 64;
            __nv_bfloat16* arow = a_bf + t * ALD2;
#pragma unroll
            for (int c = 0; c < 16; c++) {
                float4 v = row[c];
                int k = kb0 + 4 * c;
                *(unsigned int*)(arow + k)     = bf16x2_of(v.x, v.y);
                *(unsigned int*)(arow + k + 2) = bf16x2_of(v.z, v.w);
            }
        }
    }
    __syncthreads();

    // ---- layer 1: D1[112x80] = A[112x128] @ weff^T (bf16 wmma) ----
    wmma::fragment<wmma::accumulator, 16, 16, 16, float> acc1[5];
    if (wid < 7) {
#pragma unroll
        for (int nt = 0; nt < 5; nt++) wmma::fill_fragment(acc1[nt], 0.0f);
#pragma unroll
        for (int ks = 0; ks < 8; ks++) {
            wmma::fragment<wmma::matrix_a, 16, 16, 16, __nv_bfloat16, wmma::row_major> af;
            wmma::load_matrix_sync(af, a_bf + wid * 16 * ALD2 + ks * 16, ALD2);
#pragma unroll
            for (int nt = 0; nt < 5; nt++) {
                wmma::fragment<wmma::matrix_b, 16, 16, 16, __nv_bfloat16, wmma::col_major> bf;
                wmma::load_matrix_sync(bf, b1s + nt * 16 * ALD2 + ks * 16, ALD2);
                wmma::mma_sync(acc1[nt], af, bf, acc1[nt]);
            }
        }
    }
    __syncthreads();   // A + B1 dead; accumulators in regs
    if (wid < 7) {
#pragma unroll
        for (int nt = 0; nt < 5; nt++)
            wmma::store_matrix_sync(d1f + wid * 16 * D1LD + nt * 16, acc1[nt], D1LD,
                                    wmma::mem_row_major);
    }
    __syncthreads();

    // ---- epilogue 1: S1 = sigf(D1 + cq) bf16 ----
    for (int i = tid; i < THP * D1; i += 256) {
        int t = i / D1, j = i - t * D1;
        s1p[t * S1LD + j] = __float2bfloat16(sigf(d1f[t * D1LD + j] + cqs[j]));
    }
    __syncthreads();

    // ---- layer 2: D2[112x48] = S1[112x80] @ B2^T (bf16 wmma) ----
    for (int idx = wid; idx < 7 * 3; idx += 8) {
        int mt = idx / 3, nt = idx - 3 * mt;
        wmma::fragment<wmma::accumulator, 16, 16, 16, float> acc2;
        wmma::fill_fragment(acc2, 0.0f);
#pragma unroll
        for (int ks = 0; ks < 5; ks++) {
            wmma::fragment<wmma::matrix_a, 16, 16, 16, __nv_bfloat16, wmma::row_major> af;
            wmma::fragment<wmma::matrix_b, 16, 16, 16, __nv_bfloat16, wmma::col_major> bf;
            wmma::load_matrix_sync(af, s1p + mt * 16 * S1LD + ks * 16, S1LD);
            wmma::load_matrix_sync(bf, b2s + nt * 16 * S1LD + ks * 16, S1LD);
            wmma::mma_sync(acc2, af, bf, acc2);
        }
        wmma::store_matrix_sync(d2f + mt * 16 * D2LD + nt * 16, acc2, D2LD,
                                wmma::mem_row_major);
    }
    __syncthreads();

    // ---- layer 3: raw masked score -> g_attn ----
    if (tid < TH) {
        int tg = h0 + tid;
        float sc;
        if (tg < len) {
            float score = b3[0];
            const float* dr = d2f + tid * D2LD;
#pragma unroll
            for (int n = 0; n < D2; n++)
                score = fmaf(sigf(dr[n] + b2v[n]), w3s[n], score);
            sc = score * RSQRT_K;
        } else {
            sc = MASKV * RSQRT_K;
        }
        g_attn[b * 224 + tg] = sc;
    }
}

// =====================================================================
// ATT-B: softmax over raw scores + exact fp32 weighted embedding bag
// =====================================================================
__global__ __launch_bounds__(256) void attnbag_kernel(
    const int* __restrict__ history, const int* __restrict__ length,
    const int* __restrict__ cate_list,
    const float* __restrict__ item_table, const float* __restrict__ cate_table)
{
    __shared__ float part[8][128];
    __shared__ float red[256];
    __shared__ float attn_s[224];
    const int b = blockIdx.x;
    const int tid = threadIdx.x;
    const int lane = tid & 31, w = tid >> 5;
    const int len = length[b];

    // softmax over t < 200
    float sc = (tid < TT) ? g_attn[b * 224 + tid] : -FLT_MAX;
    red[tid] = sc;
    __syncthreads();
#pragma unroll
    for (int s = 128; s > 0; s >>= 1) {
        if (tid < s) red[tid] = fmaxf(red[tid], red[tid + s]);
        __syncthreads();
    }
    const float mx = red[0];
    __syncthreads();
    float p = (tid < TT) ? __expf(sc - mx) : 0.0f;
    red[tid] = p;
    __syncthreads();
#pragma unroll
    for (int s = 128; s > 0; s >>= 1) {
        if (tid < s) red[tid] += red[tid + s];
        __syncthreads();
    }
    const float inv = 1.0f / red[0];
    if (tid < 224) attn_s[tid] = (tid < TT) ? p * inv : 0.0f;
    __syncthreads();

    // bag
    float4 acc = make_float4(0.f, 0.f, 0.f, 0.f);
    for (int t = w; t < len; t += 8) {
        float a = attn_s[t];
        int hidx = history[b * TT + t];
        const float4* row = (lane < 16)
            ? (const float4*)(item_table + (size_t)hidx * 64) + lane
            : (const float4*)(cate_table + (size_t)cate_list[hidx] * 64) + (lane - 16);
        float4 v = *row;
        acc.x = fmaf(a, v.x, acc.x);
        acc.y = fmaf(a, v.y, acc.y);
        acc.z = fmaf(a, v.z, acc.z);
        acc.w = fmaf(a, v.w, acc.w);
    }
    ((float4*)part[w])[lane] = acc;
    __syncthreads();
    if (tid < 128) {
        float s = 0.f;
#pragma unroll
        for (int i = 0; i < 8; i++) s += part[i][tid];
        g_hist_attn[b * KK + tid] = s;
    }
}

// =====================================================================
// final: dice + fc3 + item bias + sigmoid
// =====================================================================
__global__ void final_k(const float* __restrict__ W3, const float* __restrict__ b3,
                        const float* __restrict__ alpha, const float* __restrict__ beta,
                        float* __restrict__ out, int out_size)
{
    int b = blockIdx.x * blockDim.x + threadIdx.x;
    if (b >= BB) return;
    float acc = b3[0];
#pragma unroll
    for (int k = 0; k < D2; k++) {
        float v  = g_y2[b * D2 + k];
        float xn = (v - g_m4[k]) * g_r4[k];
        float pp = sigf(beta[k] * xn);
        v = v * (pp + alpha[k] * (1.0f - pp));
        acc = fmaf(v, W3[k], acc);
    }
    acc += g_obias[b];
    if (b < out_size) out[b] = acc;
    if (BB + b < out_size) out[BB + b] = sigf_precise(acc);
}

// =====================================================================
// launch
// =====================================================================
extern "C" void kernel_launch(void* const* d_in, const int* in_sizes, int n_in,
                              void* d_out, int out_size)
{
    const int*   user       = (const int*)  d_in[0];
    const int*   item       = (const int*)  d_in[1];
    const int*   history    = (const int*)  d_in[2];
    const int*   length     = (const int*)  d_in[3];
    const int*   cate_list  = (const int*)  d_in[4];
    const float* user_table = (const float*)d_in[5];
    const float* item_table = (const float*)d_in[6];
    const float* cate_table = (const float*)d_in[7];
    const float* item_bias  = (const float*)d_in[8];
    const float* att_W1     = (const float*)d_in[9];
    const float* att_b1     = (const float*)d_in[10];
    const float* att_W2     = (const float*)d_in[11];
    const float* att_b2     = (const float*)d_in[12];
    const float* att_W3     = (const float*)d_in[13];
    const float* att_b3     = (const float*)d_in[14];
    const float* hbn_gamma  = (const float*)d_in[15];
    const float* hbn_beta   = (const float*)d_in[16];
    const float* hist_W     = (const float*)d_in[17];
    const float* hist_b     = (const float*)d_in[18];
    const float* fbn_gamma  = (const float*)d_in[19];
    const float* fbn_beta   = (const float*)d_in[20];
    const float* fc1_W      = (const float*)d_in[21];
    const float* fc1_b      = (const float*)d_in[22];
    const float* d1_alpha   = (const float*)d_in[23];
    const float* d1_beta    = (const float*)d_in[24];
    const float* fc2_W      = (const float*)d_in[25];
    const float* fc2_b      = (const float*)d_in[26];
    const float* d2_alpha   = (const float*)d_in[27];
    const float* d2_beta    = (const float*)d_in[28];
    const float* fc3_W      = (const float*)d_in[29];
    const float* fc3_b      = (const float*)d_in[30];
    float* out = (float*)d_out;

    float *p_q, *p_cq, *p_wac, *p_ha, *p_join, *p_y1, *p_y2;
    float *p_m1, *p_r1, *p_m2, *p_r2, *p_m3, *p_r3, *p_m4, *p_r4;
    cudaGetSymbolAddress((void**)&p_q,    g_q);
    cudaGetSymbolAddress((void**)&p_cq,   g_cq);
    cudaGetSymbolAddress((void**)&p_wac,  g_Wac);
    cudaGetSymbolAddress((void**)&p_ha,   g_hist_attn);
    cudaGetSymbolAddress((void**)&p_join, g_join);
    cudaGetSymbolAddress((void**)&p_y1,   g_y1);
    cudaGetSymbolAddress((void**)&p_y2,   g_y2);
    cudaGetSymbolAddress((void**)&p_m1,   g_m1);
    cudaGetSymbolAddress((void**)&p_r1,   g_r1);
    cudaGetSymbolAddress((void**)&p_m2,   g_m2);
    cudaGetSymbolAddress((void**)&p_r2,   g_r2);
    cudaGetSymbolAddress((void**)&p_m3,   g_m3);
    cudaGetSymbolAddress((void**)&p_r3,   g_r3);
    cudaGetSymbolAddress((void**)&p_m4,   g_m4);
    cudaGetSymbolAddress((void**)&p_r4,   g_r4);

    cudaFuncSetAttribute(att_kernel, cudaFuncAttributeMaxDynamicSharedMemorySize,
                         SMEM_ATT_TOTAL);

    auto smemG = [](int KIN, int JOUT) { return (JOUT + 18) * (KIN + 2) * 4; };
    cudaFuncSetAttribute((const void*)gemm_smemW<128, 80, 0>,
        cudaFuncAttributeMaxDynamicSharedMemorySize, smemG(128, 80));
    cudaFuncSetAttribute((const void*)gemm_smemW<128, 128, 1>,
        cudaFuncAttributeMaxDynamicSharedMemorySize, smemG(128, 128));
    cudaFuncSetAttribute((const void*)gemm_smemW<384, 80, 1>,
        cudaFuncAttributeMaxDynamicSharedMemorySize, smemG(384, 80));
    cudaFuncSetAttribute((const void*)gemm_smemW<80, 40, 2>,
        cudaFuncAttributeMaxDynamicSharedMemorySize, smemG(80, 40));

    // 1-3: prep (att lands in profile slot 4)
    fold_W<<<(KK * D1 + 255) / 256, 256>>>(att_W1, att_W2);
    prep_batch<<<BB, 128>>>(user, item, cate_list, user_table, item_table,
                            cate_table, item_bias);
    gemm_smemW<128, 80, 0><<<BB / 16, 256, smemG(128, 80)>>>(
        p_q, KK, p_wac, att_b1, p_cq, D1, 0, nullptr, nullptr, nullptr, nullptr);

    // 4: ATT-A (half-batch per CTA, raw scores; 2 CTAs/SM)
    att_kernel<<<2 * BB, 256, SMEM_ATT_TOTAL>>>(history, length, cate_list,
                                                item_table, cate_table, att_W1,
                                                att_b2, att_W3, att_b3);
    // 5: ATT-B (softmax + exact fp32 weighted embedding bag)
    attnbag_kernel<<<BB, 256>>>(history, length, cate_list, item_table, cate_table);

    // tail
    colstats2<<<(KK + 31) / 32, 512>>>(p_ha, BB, KK, p_m1, p_r1);
    gemm_smemW<128, 128, 1><<<BB / 16, 256, smemG(128, 128)>>>(
        p_ha, KK, hist_W, hist_b, p_join, DJ, 256, p_m1, p_r1, hbn_gamma, hbn_beta);
    colstats2<<<(DJ + 31) / 32, 512>>>(p_join, BB, DJ, p_m2, p_r2);
    gemm_smemW<384, 80, 1><<<BB / 16, 256, smemG(384, 80)>>>(
        p_join, DJ, fc1_W, fc1_b, p_y1, D1, 0, p_m2, p_r2, fbn_gamma, fbn_beta);
    colstats2<<<(D1 + 31) / 32, 512>>>(p_y1, BB, D1, p_m3, p_r3);
    gemm_smemW<80, 40, 2><<<BB / 16, 256, smemG(80, 40)>>>(
        p_y1, D1, fc2_W, fc2_b, p_y2, D2, 0, p_m3, p_r3, d1_alpha, d1_beta);
    colstats2<<<(D2 + 31) / 32, 512>>>(p_y2, BB, D2, p_m4, p_r4);
    final_k<<<(BB + 255) / 256, 256>>>(fc3_W, fc3_b, d2_alpha, d2_beta, out, out_size);
}